// round 10
// baseline (speedup 1.0000x reference)
#include <cuda_runtime.h>
#include <stdint.h>

#define F_IN  512
#define F_HID 128
#define F_OUT 64
#define N_MAX 100000
#define E_MAX 1600000

// ---------------- scratch (device globals; no allocation allowed) ----------
__device__ int   g_is64;
__device__ int   g_deg   [N_MAX];
__device__ int   g_cursor[N_MAX];
__device__ int   g_off   [N_MAX + 1];
__device__ float g_dinv  [N_MAX];
__device__ int2  g_csr   [E_MAX];            // .x = src, .y = bits(norm weight)
__device__ float g_h1  [(size_t)N_MAX * F_HID];
__device__ float g_a1  [(size_t)N_MAX * F_HID];
__device__ float g_h2  [(size_t)N_MAX * F_OUT];

// ---------------- init + edge-index dtype detection (merged) -----------------
// int64 non-negative values < 2^31  =>  every odd 32-bit word is 0.
__global__ void init_detect(const int* __restrict__ w, int n_words, int N) {
    int i = blockIdx.x * blockDim.x + threadIdx.x;
    if (i < N) { g_deg[i] = 1; g_cursor[i] = 0; }   // self-loop counted
    if (blockIdx.x == 0) {
        __shared__ int any;
        if (threadIdx.x == 0) any = 0;
        __syncthreads();
        int lim = min(2048, n_words / 2);
        for (int j = threadIdx.x; j < lim; j += blockDim.x)
            if (w[2 * j + 1] != 0) any = 1;   // benign race
        __syncthreads();
        if (threadIdx.x == 0) g_is64 = (any == 0);
    }
}
__device__ __forceinline__ int edge_at(const void* ei, long long idx) {
    if (g_is64) return (int)((const long long*)ei)[idx];
    return ((const int*)ei)[idx];
}

// ---------------- degree / scan(+dinv) / CSR build ---------------------------
__global__ void deg_count(const void* __restrict__ ei, int E) {
    int e = blockIdx.x * blockDim.x + threadIdx.x;
    if (e >= E) return;
    atomicAdd(&g_deg[edge_at(ei, (long long)E + e)], 1);
}
__global__ void scan_kernel(int N, int E) {
    __shared__ int sh[1024];
    int tid = threadIdx.x;
    int chunk = (N + 1023) >> 10;
    int st = tid * chunk, en = min(st + chunk, N);
    int s = 0;
    for (int i = st; i < en; i++) s += g_deg[i] - 1;
    sh[tid] = s;
    __syncthreads();
    for (int off = 1; off < 1024; off <<= 1) {
        int v = (tid >= off) ? sh[tid - off] : 0;
        __syncthreads();
        sh[tid] += v;
        __syncthreads();
    }
    int base = tid ? sh[tid - 1] : 0;
    for (int i = st; i < en; i++) {
        g_off[i] = base;
        int d = g_deg[i];
        base += d - 1;
        g_dinv[i] = rsqrtf((float)d);
    }
    if (tid == 0) g_off[N] = E;
}
__global__ void place_kernel(const void* __restrict__ ei, int E) {
    int e = blockIdx.x * blockDim.x + threadIdx.x;
    if (e >= E) return;
    int src = edge_at(ei, e);
    int dst = edge_at(ei, (long long)E + e);
    int pos = g_off[dst] + atomicAdd(&g_cursor[dst], 1);
    float w = g_dinv[src] * g_dinv[dst];
    g_csr[pos] = make_int2(src, __float_as_int(w));
}

// ---------------- TF32 tensor-core GEMM (ldmatrix fragments) -----------------
__device__ __forceinline__ uint32_t tf32_of(float x) {
    uint32_t u;
    asm("cvt.rna.tf32.f32 %0, %1;" : "=r"(u) : "f"(x));
    return u;
}
__device__ __forceinline__ void mma_tf32(float* d, const uint32_t* a, const uint32_t* b) {
    asm volatile(
        "mma.sync.aligned.m16n8k8.row.col.f32.tf32.tf32.f32 "
        "{%0,%1,%2,%3}, {%4,%5,%6,%7}, {%8,%9}, {%0,%1,%2,%3};"
        : "+f"(d[0]), "+f"(d[1]), "+f"(d[2]), "+f"(d[3])
        : "r"(a[0]), "r"(a[1]), "r"(a[2]), "r"(a[3]), "r"(b[0]), "r"(b[1]));
}
__device__ __forceinline__ void ldsm4(uint32_t* d, uint32_t saddr) {
    asm volatile("ldmatrix.sync.aligned.m8n8.x4.shared.b16 {%0,%1,%2,%3}, [%4];"
                 : "=r"(d[0]), "=r"(d[1]), "=r"(d[2]), "=r"(d[3]) : "r"(saddr));
}
__device__ __forceinline__ uint32_t smem_u32(const void* p) {
    return (uint32_t)__cvta_generic_to_shared(p);
}

// C[M,N] = A[M,K] @ B[K,N], row-major. 256 threads, 8 warps. N%BN==0, K%32==0.
// A staged row-major tf32 (As[r][k]); B staged n-major tf32 (Bs[n][k]).
// Fragments loaded via ldmatrix.x4 (A: 1 per mma-row-block; B: 1 per 2 n-blocks).
// Row stride 36 words (144B, 16B-aligned) -> all LDSM/STS phases conflict-free.
template <int BM, int BN, int WM, int WN>
__global__ __launch_bounds__(256, 2) void mma_gemm(const float* __restrict__ A,
                                                   const float* __restrict__ B,
                                                   float* __restrict__ C,
                                                   int M, int N, int K) {
    constexpr int BK = 32;
    constexpr int KS = 4;                     // 8-wide k-steps per tile
    constexpr int WARPS_N = BN / WN;
    constexpr int MI = WM / 16;
    constexpr int NI = WN / 8;
    constexpr int NP = NI / 2;                // ldmatrix.x4 covers 2 n-blocks
    constexpr int ST = BK + 4;                // 36-word row stride
    constexpr int NA4 = BM * (BK / 4) / 256;  // A float4 chunks per thread
    constexpr int NSPL = 256 / BN;            // threads stacked per n-column
    constexpr int KPER = BK / NSPL;           // k's per thread in B staging

    __shared__ uint32_t As[BM][ST];
    __shared__ uint32_t Bs[BN][ST];

    const int tid  = threadIdx.x;
    const int lane = tid & 31;
    const int w    = tid >> 5;
    const int wm   = w / WARPS_N;
    const int wn   = w % WARPS_N;
    const int bm0  = blockIdx.x * BM;
    const int bn0  = blockIdx.y * BN;

    // ldmatrix per-lane base addresses (constant across k-tiles)
    uint32_t a_addr[MI], b_addr[NP];
    {
        int rl = (lane & 7) + ((lane >> 3) & 1) * 8;   // row within 16-block
        int ca = ((lane >> 4) & 1) * 4;                // col half (A)
#pragma unroll
        for (int mi = 0; mi < MI; mi++)
            a_addr[mi] = smem_u32(&As[0][0]) + 4u * ((wm * WM + mi * 16 + rl) * ST + ca);
        int nl = (lane & 7) + ((lane >> 4) & 1) * 8;   // n-row within 16-block
        int cb = ((lane >> 3) & 1) * 4;                // k half (B)
#pragma unroll
        for (int p = 0; p < NP; p++)
            b_addr[p] = smem_u32(&Bs[0][0]) + 4u * ((wn * WN + p * 16 + nl) * ST + cb);
    }

    float acc[MI][NI][4];
#pragma unroll
    for (int i = 0; i < MI; i++)
#pragma unroll
        for (int j = 0; j < NI; j++)
#pragma unroll
            for (int k = 0; k < 4; k++) acc[i][j][k] = 0.f;

    const int bn_n = tid % BN;        // B staging: column owned by this thread
    const int bk_0 = (tid / BN) * KPER;

    for (int k0 = 0; k0 < K; k0 += BK) {
        // ---- stage A: coalesced float4 along k, CVT, one STS.128 ----
#pragma unroll
        for (int j = 0; j < NA4; j++) {
            int i  = tid + j * 256;
            int r  = i >> 3;
            int c4 = (i & 7) * 4;
            int gr = bm0 + r;
            float4 v = make_float4(0.f, 0.f, 0.f, 0.f);
            if (gr < M) v = *(const float4*)(A + (size_t)gr * K + k0 + c4);
            uint4 u = make_uint4(tf32_of(v.x), tf32_of(v.y), tf32_of(v.z), tf32_of(v.w));
            *(uint4*)&As[r][c4] = u;
        }
        // ---- stage B transposed: coalesced along n, CVT, vector STS ----
        {
            uint32_t buf[KPER];
#pragma unroll
            for (int kk = 0; kk < KPER; kk++)
                buf[kk] = tf32_of(B[(size_t)(k0 + bk_0 + kk) * N + bn0 + bn_n]);
#pragma unroll
            for (int q = 0; q < KPER / 4; q++)
                *(uint4*)&Bs[bn_n][bk_0 + q * 4] =
                    make_uint4(buf[q * 4], buf[q * 4 + 1], buf[q * 4 + 2], buf[q * 4 + 3]);
        }
        __syncthreads();

#pragma unroll
        for (int ks = 0; ks < KS; ks++) {
            uint32_t af[MI][4], bf[NI][2];
#pragma unroll
            for (int mi = 0; mi < MI; mi++)
                ldsm4(af[mi], a_addr[mi] + ks * 32);
#pragma unroll
            for (int p = 0; p < NP; p++) {
                uint32_t bq[4];
                ldsm4(bq, b_addr[p] + ks * 32);
                bf[2 * p][0] = bq[0]; bf[2 * p][1] = bq[1];
                bf[2 * p + 1][0] = bq[2]; bf[2 * p + 1][1] = bq[3];
            }
#pragma unroll
            for (int mi = 0; mi < MI; mi++)
#pragma unroll
                for (int ni = 0; ni < NI; ni++)
                    mma_tf32(acc[mi][ni], af[mi], bf[ni]);
        }
        __syncthreads();
    }

    // epilogue
#pragma unroll
    for (int mi = 0; mi < MI; mi++) {
#pragma unroll
        for (int ni = 0; ni < NI; ni++) {
            int r0 = bm0 + wm * WM + mi * 16 + (lane >> 2);
            int cc = bn0 + wn * WN + ni * 8 + (lane & 3) * 2;
            if (r0 < M)
                *(float2*)(C + (size_t)r0 * N + cc) = make_float2(acc[mi][ni][0], acc[mi][ni][1]);
            if (r0 + 8 < M)
                *(float2*)(C + (size_t)(r0 + 8) * N + cc) = make_float2(acc[mi][ni][2], acc[mi][ni][3]);
        }
    }
}

// ---------------- gather aggregation (warp per node, packed CSR) --------------
template <int F, bool RELU>
__global__ __launch_bounds__(256) void gather_agg(const float* __restrict__ h,
                                                  const float* __restrict__ bias,
                                                  float* __restrict__ outp, int N) {
    int node = blockIdx.x * (blockDim.x >> 5) + (threadIdx.x >> 5);
    if (node >= N) return;
    int lane = threadIdx.x & 31;
    int e = g_off[node], e1 = g_off[node + 1];
    float dn = g_dinv[node];
    float sw = dn * dn;

    if (F == 128) {
        const float4* hp = (const float4*)h;
        float4 acc = hp[(size_t)node * 32 + lane];
        acc.x *= sw; acc.y *= sw; acc.z *= sw; acc.w *= sw;
        for (; e + 4 <= e1; e += 4) {
            int2 p0 = g_csr[e],     p1 = g_csr[e + 1];
            int2 p2 = g_csr[e + 2], p3 = g_csr[e + 3];
            float w0 = __int_as_float(p0.y), w1 = __int_as_float(p1.y);
            float w2 = __int_as_float(p2.y), w3 = __int_as_float(p3.y);
            float4 v0 = hp[(size_t)p0.x * 32 + lane];
            float4 v1 = hp[(size_t)p1.x * 32 + lane];
            float4 v2 = hp[(size_t)p2.x * 32 + lane];
            float4 v3 = hp[(size_t)p3.x * 32 + lane];
            acc.x += w0 * v0.x + w1 * v1.x + w2 * v2.x + w3 * v3.x;
            acc.y += w0 * v0.y + w1 * v1.y + w2 * v2.y + w3 * v3.y;
            acc.z += w0 * v0.z + w1 * v1.z + w2 * v2.z + w3 * v3.z;
            acc.w += w0 * v0.w + w1 * v1.w + w2 * v2.w + w3 * v3.w;
        }
        for (; e < e1; e++) {
            int2 p = g_csr[e];
            float wv = __int_as_float(p.y);
            float4 v = hp[(size_t)p.x * 32 + lane];
            acc.x += wv * v.x; acc.y += wv * v.y; acc.z += wv * v.z; acc.w += wv * v.w;
        }
        float4 b = ((const float4*)bias)[lane];
        acc.x += b.x; acc.y += b.y; acc.z += b.z; acc.w += b.w;
        if (RELU) {
            acc.x = fmaxf(acc.x, 0.f); acc.y = fmaxf(acc.y, 0.f);
            acc.z = fmaxf(acc.z, 0.f); acc.w = fmaxf(acc.w, 0.f);
        }
        ((float4*)outp)[(size_t)node * 32 + lane] = acc;
    } else {  // F == 64
        const float2* hp = (const float2*)h;
        float2 acc = hp[(size_t)node * 32 + lane];
        acc.x *= sw; acc.y *= sw;
        for (; e + 4 <= e1; e += 4) {
            int2 p0 = g_csr[e],     p1 = g_csr[e + 1];
            int2 p2 = g_csr[e + 2], p3 = g_csr[e + 3];
            float w0 = __int_as_float(p0.y), w1 = __int_as_float(p1.y);
            float w2 = __int_as_float(p2.y), w3 = __int_as_float(p3.y);
            float2 v0 = hp[(size_t)p0.x * 32 + lane];
            float2 v1 = hp[(size_t)p1.x * 32 + lane];
            float2 v2 = hp[(size_t)p2.x * 32 + lane];
            float2 v3 = hp[(size_t)p3.x * 32 + lane];
            acc.x += w0 * v0.x + w1 * v1.x + w2 * v2.x + w3 * v3.x;
            acc.y += w0 * v0.y + w1 * v1.y + w2 * v2.y + w3 * v3.y;
        }
        for (; e < e1; e++) {
            int2 p = g_csr[e];
            float wv = __int_as_float(p.y);
            float2 v = hp[(size_t)p.x * 32 + lane];
            acc.x += wv * v.x; acc.y += wv * v.y;
        }
        float2 b = ((const float2*)bias)[lane];
        acc.x += b.x; acc.y += b.y;
        if (RELU) { acc.x = fmaxf(acc.x, 0.f); acc.y = fmaxf(acc.y, 0.f); }
        ((float2*)outp)[(size_t)node * 32 + lane] = acc;
    }
}

// ---------------- launch -----------------------------------------------------
extern "C" void kernel_launch(void* const* d_in, const int* in_sizes, int n_in,
                              void* d_out, int out_size) {
    const float* x  = (const float*)d_in[0];
    const void*  ei = d_in[1];
    const float* W1 = (const float*)d_in[2];
    const float* b1 = (const float*)d_in[3];
    const float* W2 = (const float*)d_in[4];
    const float* b2 = (const float*)d_in[5];
    float* out = (float*)d_out;

    const int N = in_sizes[0] / F_IN;
    const int E = in_sizes[1] / 2;

    float *h1p, *a1p, *h2p;
    cudaGetSymbolAddress((void**)&h1p, g_h1);
    cudaGetSymbolAddress((void**)&a1p, g_a1);
    cudaGetSymbolAddress((void**)&h2p, g_h2);

    init_detect<<<(N + 255) / 256, 256>>>((const int*)ei, in_sizes[1], N);
    deg_count<<<(E + 255) / 256, 256>>>(ei, E);
    scan_kernel<<<1, 1024>>>(N, E);
    place_kernel<<<(E + 255) / 256, 256>>>(ei, E);

    // Layer 1: h1 = x @ W1 ; a1 = relu(A_norm h1 + b1)
    mma_gemm<128, 128, 64, 32><<<dim3((N + 127) / 128, F_HID / 128), 256>>>(
        x, W1, h1p, N, F_HID, F_IN);
    gather_agg<F_HID, true><<<(N + 7) / 8, 256>>>(h1p, b1, a1p, N);

    // Layer 2: h2 = a1 @ W2 ; out = A_norm h2 + b2
    mma_gemm<128, 64, 32, 32><<<dim3((N + 127) / 128, F_OUT / 64), 256>>>(
        a1p, W2, h2p, N, F_OUT, F_HID);
    gather_agg<F_OUT, false><<<(N + 7) / 8, 256>>>(h2p, b2, out, N);
}

// round 11
// speedup vs baseline: 1.3896x; 1.3896x over previous
#include <cuda_runtime.h>
#include <stdint.h>

#define F_IN  512
#define F_HID 128
#define F_OUT 64
#define N_MAX 100000
#define E_MAX 1600000

// ---------------- scratch (device globals; no allocation allowed) ----------
__device__ int   g_is64;
__device__ int   g_deg   [N_MAX];
__device__ int   g_cursor[N_MAX];
__device__ int   g_off   [N_MAX + 1];
__device__ float g_dinv  [N_MAX];
__device__ int   g_csr_src[E_MAX];
__device__ float g_csr_w  [E_MAX];
__device__ float g_h1  [(size_t)N_MAX * F_HID];
__device__ float g_a1  [(size_t)N_MAX * F_HID];
__device__ float g_h2  [(size_t)N_MAX * F_OUT];

// ---------------- init + edge-index dtype detection (merged) -----------------
// int64 non-negative values < 2^31  =>  every odd 32-bit word is 0.
__global__ void init_detect(const int* __restrict__ w, int n_words, int N) {
    int i = blockIdx.x * blockDim.x + threadIdx.x;
    if (i < N) { g_deg[i] = 1; g_cursor[i] = 0; }   // self-loop counted
    if (blockIdx.x == 0) {
        __shared__ int any;
        if (threadIdx.x == 0) any = 0;
        __syncthreads();
        int lim = min(2048, n_words / 2);
        for (int j = threadIdx.x; j < lim; j += blockDim.x)
            if (w[2 * j + 1] != 0) any = 1;   // benign race
        __syncthreads();
        if (threadIdx.x == 0) g_is64 = (any == 0);
    }
}
__device__ __forceinline__ int edge_at(const void* ei, long long idx) {
    if (g_is64) return (int)((const long long*)ei)[idx];
    return ((const int*)ei)[idx];
}

// ---------------- degree / scan(+dinv) / CSR build ---------------------------
__global__ void deg_count(const void* __restrict__ ei, int E) {
    int e = blockIdx.x * blockDim.x + threadIdx.x;
    if (e >= E) return;
    atomicAdd(&g_deg[edge_at(ei, (long long)E + e)], 1);
}
__global__ void scan_kernel(int N, int E) {
    __shared__ int sh[1024];
    int tid = threadIdx.x;
    int chunk = (N + 1023) >> 10;
    int st = tid * chunk, en = min(st + chunk, N);
    int s = 0;
    for (int i = st; i < en; i++) s += g_deg[i] - 1;
    sh[tid] = s;
    __syncthreads();
    for (int off = 1; off < 1024; off <<= 1) {
        int v = (tid >= off) ? sh[tid - off] : 0;
        __syncthreads();
        sh[tid] += v;
        __syncthreads();
    }
    int base = tid ? sh[tid - 1] : 0;
    for (int i = st; i < en; i++) {
        g_off[i] = base;
        int d = g_deg[i];
        base += d - 1;
        g_dinv[i] = rsqrtf((float)d);
    }
    if (tid == 0) g_off[N] = E;
}
__global__ void place_kernel(const void* __restrict__ ei, int E) {
    int e = blockIdx.x * blockDim.x + threadIdx.x;
    if (e >= E) return;
    int src = edge_at(ei, e);
    int dst = edge_at(ei, (long long)E + e);
    int pos = g_off[dst] + atomicAdd(&g_cursor[dst], 1);
    g_csr_src[pos] = src;
    g_csr_w[pos]   = g_dinv[src] * g_dinv[dst];
}

// ---------------- TF32 tensor-core GEMM (R2 skeleton, A pair-interleaved) ----
__device__ __forceinline__ uint32_t tf32_of(float x) {
    uint32_t u;
    asm("cvt.rna.tf32.f32 %0, %1;" : "=r"(u) : "f"(x));
    return u;
}
__device__ __forceinline__ void mma_tf32(float* d, const uint32_t* a, const uint32_t* b) {
    asm volatile(
        "mma.sync.aligned.m16n8k8.row.col.f32.tf32.tf32.f32 "
        "{%0,%1,%2,%3}, {%4,%5,%6,%7}, {%8,%9}, {%0,%1,%2,%3};"
        : "+f"(d[0]), "+f"(d[1]), "+f"(d[2]), "+f"(d[3])
        : "r"(a[0]), "r"(a[1]), "r"(a[2]), "r"(a[3]), "r"(b[0]), "r"(b[1]));
}

// C[M,N] = A[M,K] @ B[K,N], row-major. 256 threads, 8 warps. N%BN==0, K%32==0.
// Both tiles staged tf32-rounded. A row layout is (q,h)-pair interleaved:
//   logical column c = ks*8 + h*4 + q  ->  storage word ks*8 + q*2 + h
// so the mma A-fragment pair (c, c+4) is one aligned 8-byte LDS.64.
template <int BM, int BN, int WM, int WN>
__global__ __launch_bounds__(256, 2) void mma_gemm(const float* __restrict__ A,
                                                   const float* __restrict__ B,
                                                   float* __restrict__ C,
                                                   int M, int N, int K) {
    constexpr int BK = 32;
    constexpr int KS = BK / 8;           // 4
    constexpr int WARPS_N = BN / WN;
    constexpr int MI = WM / 16;
    constexpr int NI = WN / 8;
    constexpr int APAD = 4;              // row stride 36 words: banks 4r+... distinct
    constexpr int BPAD = 8;              // row stride ≡ 8 mod 32: banks 8r+n distinct

    __shared__ uint32_t As[BM][BK + APAD];
    __shared__ uint32_t Bs[BK][BN + BPAD];

    const int tid  = threadIdx.x;
    const int lane = tid & 31;
    const int w    = tid >> 5;
    const int wm   = w / WARPS_N;
    const int wn   = w % WARPS_N;
    const int bm0  = blockIdx.x * BM;
    const int bn0  = blockIdx.y * BN;

    float acc[MI][NI][4];
#pragma unroll
    for (int i = 0; i < MI; i++)
#pragma unroll
        for (int j = 0; j < NI; j++)
#pragma unroll
            for (int k = 0; k < 4; k++) acc[i][j][k] = 0.f;

    for (int k0 = 0; k0 < K; k0 += BK) {
        // ---- stage A (tf32, pair-interleaved columns) ----
#pragma unroll
        for (int i = tid; i < BM * BK / 4; i += 256) {
            int idx = i * 4;
            int r   = idx / BK;
            int c4  = idx % BK;          // multiple of 4: ks,h fixed; q = 0..3
            float4 v = make_float4(0.f, 0.f, 0.f, 0.f);
            int gr = bm0 + r;
            if (gr < M) v = *(const float4*)(A + (size_t)gr * K + k0 + c4);
            int ks = c4 >> 3, h = (c4 >> 2) & 1;
            int base = ks * 8 + h;
            As[r][base + 0] = tf32_of(v.x);
            As[r][base + 2] = tf32_of(v.y);
            As[r][base + 4] = tf32_of(v.z);
            As[r][base + 6] = tf32_of(v.w);
        }
        // ---- stage B (tf32, plain layout) ----
#pragma unroll
        for (int i = tid; i < BK * BN / 4; i += 256) {
            int idx = i * 4;
            int r   = idx / BN;
            int c4  = idx % BN;
            float4 v = *(const float4*)(B + (size_t)(k0 + r) * N + bn0 + c4);
            Bs[r][c4 + 0] = tf32_of(v.x);
            Bs[r][c4 + 1] = tf32_of(v.y);
            Bs[r][c4 + 2] = tf32_of(v.z);
            Bs[r][c4 + 3] = tf32_of(v.w);
        }
        __syncthreads();

#pragma unroll
        for (int ks = 0; ks < KS; ks++) {
            uint32_t af[MI][4], bf[NI][2];
            const int q = lane & 3;
#pragma unroll
            for (int mi = 0; mi < MI; mi++) {
                int r0 = wm * WM + mi * 16 + (lane >> 2);
                uint2 lo = *(const uint2*)&As[r0][ks * 8 + q * 2];
                uint2 hi = *(const uint2*)&As[r0 + 8][ks * 8 + q * 2];
                af[mi][0] = lo.x; af[mi][1] = hi.x;
                af[mi][2] = lo.y; af[mi][3] = hi.y;
            }
            const int br = ks * 8 + q;
#pragma unroll
            for (int ni = 0; ni < NI; ni++) {
                int n0 = wn * WN + ni * 8 + (lane >> 2);
                bf[ni][0] = Bs[br][n0];
                bf[ni][1] = Bs[br + 4][n0];
            }
#pragma unroll
            for (int mi = 0; mi < MI; mi++)
#pragma unroll
                for (int ni = 0; ni < NI; ni++)
                    mma_tf32(acc[mi][ni], af[mi], bf[ni]);
        }
        __syncthreads();
    }

    // epilogue
#pragma unroll
    for (int mi = 0; mi < MI; mi++) {
#pragma unroll
        for (int ni = 0; ni < NI; ni++) {
            int r0 = bm0 + wm * WM + mi * 16 + (lane >> 2);
            int cc = bn0 + wn * WN + ni * 8 + (lane & 3) * 2;
            if (r0 < M)
                *(float2*)(C + (size_t)r0 * N + cc) = make_float2(acc[mi][ni][0], acc[mi][ni][1]);
            if (r0 + 8 < M)
                *(float2*)(C + (size_t)(r0 + 8) * N + cc) = make_float2(acc[mi][ni][2], acc[mi][ni][3]);
        }
    }
}

// ---------------- gather aggregation (warp per node) --------------------------
template <int F, bool RELU>
__global__ __launch_bounds__(256) void gather_agg(const float* __restrict__ h,
                                                  const float* __restrict__ bias,
                                                  float* __restrict__ outp, int N) {
    int node = blockIdx.x * (blockDim.x >> 5) + (threadIdx.x >> 5);
    if (node >= N) return;
    int lane = threadIdx.x & 31;
    int e = g_off[node], e1 = g_off[node + 1];
    float dn = g_dinv[node];
    float sw = dn * dn;

    if (F == 128) {
        const float4* hp = (const float4*)h;
        float4 acc = hp[(size_t)node * 32 + lane];
        acc.x *= sw; acc.y *= sw; acc.z *= sw; acc.w *= sw;
        for (; e + 4 <= e1; e += 4) {
            int s0 = g_csr_src[e], s1 = g_csr_src[e + 1];
            int s2 = g_csr_src[e + 2], s3 = g_csr_src[e + 3];
            float w0 = g_csr_w[e], w1 = g_csr_w[e + 1];
            float w2 = g_csr_w[e + 2], w3 = g_csr_w[e + 3];
            float4 v0 = hp[(size_t)s0 * 32 + lane];
            float4 v1 = hp[(size_t)s1 * 32 + lane];
            float4 v2 = hp[(size_t)s2 * 32 + lane];
            float4 v3 = hp[(size_t)s3 * 32 + lane];
            acc.x += w0 * v0.x + w1 * v1.x + w2 * v2.x + w3 * v3.x;
            acc.y += w0 * v0.y + w1 * v1.y + w2 * v2.y + w3 * v3.y;
            acc.z += w0 * v0.z + w1 * v1.z + w2 * v2.z + w3 * v3.z;
            acc.w += w0 * v0.w + w1 * v1.w + w2 * v2.w + w3 * v3.w;
        }
        for (; e < e1; e++) {
            int s = g_csr_src[e];
            float wv = g_csr_w[e];
            float4 v = hp[(size_t)s * 32 + lane];
            acc.x += wv * v.x; acc.y += wv * v.y; acc.z += wv * v.z; acc.w += wv * v.w;
        }
        float4 b = ((const float4*)bias)[lane];
        acc.x += b.x; acc.y += b.y; acc.z += b.z; acc.w += b.w;
        if (RELU) {
            acc.x = fmaxf(acc.x, 0.f); acc.y = fmaxf(acc.y, 0.f);
            acc.z = fmaxf(acc.z, 0.f); acc.w = fmaxf(acc.w, 0.f);
        }
        ((float4*)outp)[(size_t)node * 32 + lane] = acc;
    } else {  // F == 64
        const float2* hp = (const float2*)h;
        float2 acc = hp[(size_t)node * 32 + lane];
        acc.x *= sw; acc.y *= sw;
        for (; e + 4 <= e1; e += 4) {
            int s0 = g_csr_src[e], s1 = g_csr_src[e + 1];
            int s2 = g_csr_src[e + 2], s3 = g_csr_src[e + 3];
            float w0 = g_csr_w[e], w1 = g_csr_w[e + 1];
            float w2 = g_csr_w[e + 2], w3 = g_csr_w[e + 3];
            float2 v0 = hp[(size_t)s0 * 32 + lane];
            float2 v1 = hp[(size_t)s1 * 32 + lane];
            float2 v2 = hp[(size_t)s2 * 32 + lane];
            float2 v3 = hp[(size_t)s3 * 32 + lane];
            acc.x += w0 * v0.x + w1 * v1.x + w2 * v2.x + w3 * v3.x;
            acc.y += w0 * v0.y + w1 * v1.y + w2 * v2.y + w3 * v3.y;
        }
        for (; e < e1; e++) {
            int s = g_csr_src[e];
            float wv = g_csr_w[e];
            float2 v = hp[(size_t)s * 32 + lane];
            acc.x += wv * v.x; acc.y += wv * v.y;
        }
        float2 b = ((const float2*)bias)[lane];
        acc.x += b.x; acc.y += b.y;
        if (RELU) { acc.x = fmaxf(acc.x, 0.f); acc.y = fmaxf(acc.y, 0.f); }
        ((float2*)outp)[(size_t)node * 32 + lane] = acc;
    }
}

// ---------------- launch -----------------------------------------------------
extern "C" void kernel_launch(void* const* d_in, const int* in_sizes, int n_in,
                              void* d_out, int out_size) {
    const float* x  = (const float*)d_in[0];
    const void*  ei = d_in[1];
    const float* W1 = (const float*)d_in[2];
    const float* b1 = (const float*)d_in[3];
    const float* W2 = (const float*)d_in[4];
    const float* b2 = (const float*)d_in[5];
    float* out = (float*)d_out;

    const int N = in_sizes[0] / F_IN;
    const int E = in_sizes[1] / 2;

    float *h1p, *a1p, *h2p;
    cudaGetSymbolAddress((void**)&h1p, g_h1);
    cudaGetSymbolAddress((void**)&a1p, g_a1);
    cudaGetSymbolAddress((void**)&h2p, g_h2);

    init_detect<<<(N + 255) / 256, 256>>>((const int*)ei, in_sizes[1], N);
    deg_count<<<(E + 255) / 256, 256>>>(ei, E);
    scan_kernel<<<1, 1024>>>(N, E);
    place_kernel<<<(E + 255) / 256, 256>>>(ei, E);

    // Layer 1: h1 = x @ W1 ; a1 = relu(A_norm h1 + b1)
    mma_gemm<128, 128, 64, 32><<<dim3((N + 127) / 128, F_HID / 128), 256>>>(
        x, W1, h1p, N, F_HID, F_IN);
    gather_agg<F_HID, true><<<(N + 7) / 8, 256>>>(h1p, b1, a1p, N);

    // Layer 2: h2 = a1 @ W2 ; out = A_norm h2 + b2
    mma_gemm<128, 64, 32, 32><<<dim3((N + 127) / 128, F_OUT / 64), 256>>>(
        a1p, W2, h2p, N, F_OUT, F_HID);
    gather_agg<F_OUT, false><<<(N + 7) / 8, 256>>>(h2p, b2, out, N);
}